// round 5
// baseline (speedup 1.0000x reference)
#include <cuda_runtime.h>
#include <cstdint>
#include <math.h>

// Problem constants (fixed shapes per reference setup_inputs)
#define TT   4096          // tokens
#define DD   2048          // model dim
#define HH   5632          // hidden dim
#define NE   8             // experts
#define BM   64            // GEMM M tile
#define MAXSLOT (TT*2 + NE*BM)   // 8704: worst-case padded slot count

// ---------------- device scratch (static: no allocations allowed) ----------
__device__ __align__(128) float g_h[(size_t)MAXSLOT * HH];   // SwiGLU activations per slot
__device__ int   g_tok[MAXSLOT];
__device__ float g_gate[MAXSLOT];      // 0.0f == padding slot sentinel
__device__ int   g_cnt[NE];
__device__ int   g_padbase[NE + 1];
__device__ int   g_ce[TT * 2];
__device__ int   g_cpos[TT * 2];
__device__ float g_cw[TT * 2];

// ---------------- init ------------------------------------------------------
__global__ void k_init() {
    int i = blockIdx.x * blockDim.x + threadIdx.x;
    if (i < NE) g_cnt[i] = 0;
    if (i < MAXSLOT) { g_tok[i] = 0; g_gate[i] = 0.0f; }
}

// ---------------- gate: logits + top-2 + softmax + per-expert counting -----
__global__ void k_gate(const float* __restrict__ x, const float* __restrict__ Wg) {
    int gtid = blockIdx.x * blockDim.x + threadIdx.x;
    int t    = gtid >> 5;          // one warp per token
    int lane = gtid & 31;
    if (t >= TT) return;

    const float* xr = x + (size_t)t * DD;
    float acc[NE];
#pragma unroll
    for (int e = 0; e < NE; e++) acc[e] = 0.0f;

    for (int k = lane; k < DD; k += 32) {
        float xv = xr[k];
        const float* wr = Wg + (size_t)k * NE;
        float4 w0 = *(const float4*)(wr);
        float4 w1 = *(const float4*)(wr + 4);
        acc[0] += xv * w0.x; acc[1] += xv * w0.y;
        acc[2] += xv * w0.z; acc[3] += xv * w0.w;
        acc[4] += xv * w1.x; acc[5] += xv * w1.y;
        acc[6] += xv * w1.z; acc[7] += xv * w1.w;
    }
#pragma unroll
    for (int off = 16; off > 0; off >>= 1) {
#pragma unroll
        for (int e = 0; e < NE; e++)
            acc[e] += __shfl_xor_sync(0xffffffff, acc[e], off);
    }

    if (lane == 0) {
        // top-1 (lowest index wins ties, matching lax.top_k)
        float l0 = acc[0]; int e0 = 0;
#pragma unroll
        for (int e = 1; e < NE; e++) if (acc[e] > l0) { l0 = acc[e]; e0 = e; }
        // top-2
        float l1 = -3.4e38f; int e1 = 0;
#pragma unroll
        for (int e = 0; e < NE; e++)
            if (e != e0 && acc[e] > l1) { l1 = acc[e]; e1 = e; }

        float wa = 1.0f / (1.0f + expf(l1 - l0));   // softmax over {l0,l1}, l0>=l1
        float wb = 1.0f - wa;

        int p0 = atomicAdd(&g_cnt[e0], 1);
        int p1 = atomicAdd(&g_cnt[e1], 1);
        int i0 = t * 2, i1 = t * 2 + 1;
        g_ce[i0] = e0; g_cpos[i0] = p0; g_cw[i0] = wa;
        g_ce[i1] = e1; g_cpos[i1] = p1; g_cw[i1] = wb;
    }
}

// ---------------- scan: padded per-expert bases -----------------------------
__global__ void k_scan() {
    int b = 0;
    g_padbase[0] = 0;
    for (int e = 0; e < NE; e++) {
        b += ((g_cnt[e] + BM - 1) / BM) * BM;
        g_padbase[e + 1] = b;
    }
}

// ---------------- scatter: slot tables --------------------------------------
__global__ void k_scatter() {
    int i = blockIdx.x * blockDim.x + threadIdx.x;
    if (i >= TT * 2) return;
    int e = g_ce[i];
    int slot = g_padbase[e] + g_cpos[i];
    g_tok[slot]  = i >> 1;
    g_gate[slot] = g_cw[i];
}

// ---------------- out = next_r ----------------------------------------------
__global__ void k_copy(float* __restrict__ out, const float* __restrict__ nr) {
    size_t i = (size_t)blockIdx.x * blockDim.x + threadIdx.x;
    if (i < (size_t)TT * DD / 4)
        ((float4*)out)[i] = ((const float4*)nr)[i];
}

// ---------------- GEMM1: h = silu(Xg @ w1[e]) * (Xg @ w3[e]) ----------------
// Tile: 64(M) x 128(N over H) x 16(K over D). 256 threads, thread tile 4x8 x2.
#define G1_LOADS(KT)                                                              \
    do {                                                                          \
        int k0_ = (KT) * 16;                                                      \
        pa  = *(const float4*)(xp + k0_);                                         \
        p1a = *(const float4*)(w1e + (size_t)(k0_ + wr0)     * HH + nc);          \
        p1b = *(const float4*)(w1e + (size_t)(k0_ + wr0 + 8) * HH + nc);          \
        p3a = *(const float4*)(w3e + (size_t)(k0_ + wr0)     * HH + nc);          \
        p3b = *(const float4*)(w3e + (size_t)(k0_ + wr0 + 8) * HH + nc);          \
    } while (0)

__global__ __launch_bounds__(256) void k_gemm1(const float* __restrict__ x,
                                               const float* __restrict__ w1,
                                               const float* __restrict__ w3) {
    __shared__ float Xs[16][BM];
    __shared__ float W1s[16][128];
    __shared__ float W3s[16][128];

    int m0 = blockIdx.x * BM;
    int total = g_padbase[NE];
    if (m0 >= total) return;
    int e = 0;
    while (g_padbase[e + 1] <= m0) e++;
    int n0 = blockIdx.y * 128;

    const float* w1e = w1 + (size_t)e * DD * HH;
    const float* w3e = w3 + (size_t)e * DD * HH;

    int tid = threadIdx.x;
    // X loader: row lr (0..63), quad lq (0..3)
    int lr = tid >> 2, lq = tid & 3;
    const float* xp = x + (size_t)g_tok[m0 + lr] * DD + lq * 4;
    // W loader: row wr0 (0..7) (+8 for second load), col nc
    int wr0 = tid >> 5;
    int nc  = n0 + (tid & 31) * 4;
    int sc  = (tid & 31) * 4;

    float acc1[4][8], acc3[4][8];
#pragma unroll
    for (int i = 0; i < 4; i++)
#pragma unroll
        for (int j = 0; j < 8; j++) { acc1[i][j] = 0.0f; acc3[i][j] = 0.0f; }

    float4 pa, p1a, p1b, p3a, p3b;
    G1_LOADS(0);

    const int NSTEP = DD / 16;   // 128
    int ty = tid >> 4, tx = tid & 15;

    for (int kt = 0; kt < NSTEP; kt++) {
        // commit prefetched tile to smem
        Xs[lq * 4 + 0][lr] = pa.x;
        Xs[lq * 4 + 1][lr] = pa.y;
        Xs[lq * 4 + 2][lr] = pa.z;
        Xs[lq * 4 + 3][lr] = pa.w;
        *(float4*)&W1s[wr0][sc]     = p1a;
        *(float4*)&W1s[wr0 + 8][sc] = p1b;
        *(float4*)&W3s[wr0][sc]     = p3a;
        *(float4*)&W3s[wr0 + 8][sc] = p3b;
        __syncthreads();

        if (kt + 1 < NSTEP) G1_LOADS(kt + 1);

#pragma unroll
        for (int kk = 0; kk < 16; kk++) {
            float4 av  = *(const float4*)&Xs[kk][ty * 4];
            float4 b1l = *(const float4*)&W1s[kk][tx * 8];
            float4 b1h = *(const float4*)&W1s[kk][tx * 8 + 4];
            float4 b3l = *(const float4*)&W3s[kk][tx * 8];
            float4 b3h = *(const float4*)&W3s[kk][tx * 8 + 4];
            float a[4]  = {av.x, av.y, av.z, av.w};
            float b1[8] = {b1l.x, b1l.y, b1l.z, b1l.w, b1h.x, b1h.y, b1h.z, b1h.w};
            float b3[8] = {b3l.x, b3l.y, b3l.z, b3l.w, b3h.x, b3h.y, b3h.z, b3h.w};
#pragma unroll
            for (int i = 0; i < 4; i++)
#pragma unroll
                for (int j = 0; j < 8; j++) {
                    acc1[i][j] += a[i] * b1[j];
                    acc3[i][j] += a[i] * b3[j];
                }
        }
        __syncthreads();
    }

    // epilogue: h = silu(acc1) * acc3  (padding rows store garbage; gated out later)
#pragma unroll
    for (int i = 0; i < 4; i++) {
        int m = m0 + ty * 4 + i;
        float* hr = g_h + (size_t)m * HH + n0 + tx * 8;
        float v[8];
#pragma unroll
        for (int j = 0; j < 8; j++) {
            float z = acc1[i][j];
            float s = z / (1.0f + expf(-z));
            v[j] = s * acc3[i][j];
        }
        *(float4*)(hr)     = make_float4(v[0], v[1], v[2], v[3]);
        *(float4*)(hr + 4) = make_float4(v[4], v[5], v[6], v[7]);
    }
}

// ---------------- GEMM2: out += gate * (h @ w2[e]) --------------------------
#define G2_LOADS(KT)                                                              \
    do {                                                                          \
        int k0_ = (KT) * 16;                                                      \
        pa  = *(const float4*)(hp + k0_);                                         \
        p2a = *(const float4*)(w2e + (size_t)(k0_ + wr0)     * DD + nc);          \
        p2b = *(const float4*)(w2e + (size_t)(k0_ + wr0 + 8) * DD + nc);          \
    } while (0)

__global__ __launch_bounds__(256) void k_gemm2(const float* __restrict__ w2,
                                               float* __restrict__ out) {
    __shared__ float Hs[16][BM];
    __shared__ float W2s[16][128];

    int m0 = blockIdx.x * BM;
    int total = g_padbase[NE];
    if (m0 >= total) return;
    int e = 0;
    while (g_padbase[e + 1] <= m0) e++;
    int n0 = blockIdx.y * 128;

    const float* w2e = w2 + (size_t)e * HH * DD;

    int tid = threadIdx.x;
    int lr = tid >> 2, lq = tid & 3;
    const float* hp = g_h + (size_t)(m0 + lr) * HH + lq * 4;
    int wr0 = tid >> 5;
    int nc  = n0 + (tid & 31) * 4;
    int sc  = (tid & 31) * 4;

    float acc[4][8];
#pragma unroll
    for (int i = 0; i < 4; i++)
#pragma unroll
        for (int j = 0; j < 8; j++) acc[i][j] = 0.0f;

    float4 pa, p2a, p2b;
    G2_LOADS(0);

    const int NSTEP = HH / 16;   // 352
    int ty = tid >> 4, tx = tid & 15;

    for (int kt = 0; kt < NSTEP; kt++) {
        Hs[lq * 4 + 0][lr] = pa.x;
        Hs[lq * 4 + 1][lr] = pa.y;
        Hs[lq * 4 + 2][lr] = pa.z;
        Hs[lq * 4 + 3][lr] = pa.w;
        *(float4*)&W2s[wr0][sc]     = p2a;
        *(float4*)&W2s[wr0 + 8][sc] = p2b;
        __syncthreads();

        if (kt + 1 < NSTEP) G2_LOADS(kt + 1);

#pragma unroll
        for (int kk = 0; kk < 16; kk++) {
            float4 av  = *(const float4*)&Hs[kk][ty * 4];
            float4 bl  = *(const float4*)&W2s[kk][tx * 8];
            float4 bh  = *(const float4*)&W2s[kk][tx * 8 + 4];
            float a[4] = {av.x, av.y, av.z, av.w};
            float b[8] = {bl.x, bl.y, bl.z, bl.w, bh.x, bh.y, bh.z, bh.w};
#pragma unroll
            for (int i = 0; i < 4; i++)
#pragma unroll
                for (int j = 0; j < 8; j++)
                    acc[i][j] += a[i] * b[j];
        }
        __syncthreads();
    }

    // epilogue: scatter-add with gate weight; gate==0 marks padding slots
#pragma unroll
    for (int i = 0; i < 4; i++) {
        int slot = m0 + ty * 4 + i;
        float gte = g_gate[slot];
        if (gte != 0.0f) {
            float* orow = out + (size_t)g_tok[slot] * DD + n0 + tx * 8;
#pragma unroll
            for (int j = 0; j < 8; j++)
                atomicAdd(&orow[j], gte * acc[i][j]);
        }
    }
}

// ---------------- launch ----------------------------------------------------
extern "C" void kernel_launch(void* const* d_in, const int* in_sizes, int n_in,
                              void* d_out, int out_size) {
    const float* x   = (const float*)d_in[0];
    const float* Wg  = (const float*)d_in[1];
    const float* w1  = (const float*)d_in[2];
    const float* w2  = (const float*)d_in[3];
    const float* w3  = (const float*)d_in[4];
    const float* nr  = (const float*)d_in[5];
    float* out = (float*)d_out;

    k_init<<<(MAXSLOT + 255) / 256, 256>>>();
    k_gate<<<TT / 8, 256>>>(x, Wg);                    // 1 warp / token
    k_scan<<<1, 1>>>();
    k_scatter<<<(TT * 2) / 256, 256>>>();
    k_copy<<<(TT * DD / 4 + 255) / 256, 256>>>(out, nr);

    dim3 g1(MAXSLOT / BM, HH / 128);                   // 136 x 44
    k_gemm1<<<g1, 256>>>(x, w1, w3);

    dim3 g2(MAXSLOT / BM, DD / 128);                   // 136 x 16
    k_gemm2<<<g2, 256>>>(w2, out);
}

// round 9
// speedup vs baseline: 4.6446x; 4.6446x over previous
#include <cuda_runtime.h>
#include <cstdint>
#include <math.h>

// ---------------- problem constants -----------------------------------------
#define TT   4096          // tokens
#define DD   2048          // model dim
#define HH   5632          // hidden dim
#define NE   8             // experts
#define BM   128           // GEMM M tile (expert padding granularity)
#define MAXSLOT (TT*2 + NE*BM)   // 9216 worst-case padded slots

// ---------------- device scratch (static: no allocs allowed) ----------------
__device__ __align__(128) float g_xg[(size_t)MAXSLOT * DD];  // gathered X rows
__device__ __align__(128) float g_h [(size_t)MAXSLOT * HH];  // SwiGLU activations
__device__ __align__(128) float g_y [(size_t)MAXSLOT * DD];  // expert outputs
__device__ int   g_tok[MAXSLOT];
__device__ int   g_cnt[NE];
__device__ int   g_padbase[NE + 1];
__device__ int   g_ce[TT * 2];
__device__ int   g_cpos[TT * 2];
__device__ float g_cw[TT * 2];
__device__ int   g_slotof[TT * 2];

// ---------------- ptx helpers -----------------------------------------------
__device__ __forceinline__ uint32_t f2tf(float f) {
    uint32_t u; asm("cvt.rna.tf32.f32 %0, %1;" : "=r"(u) : "f"(f)); return u;
}
__device__ __forceinline__ float fast_silu_mul(float z, float v) {
    float t; asm("tanh.approx.f32 %0, %1;" : "=f"(t) : "f"(z * 0.5f));
    return z * (0.5f * t + 0.5f) * v;   // z*sigmoid(z)*v
}
__device__ __forceinline__ uint32_t sh(const void* p) {
    return (uint32_t)__cvta_generic_to_shared(p);
}
#define CP16(dst, src) asm volatile("cp.async.cg.shared.global [%0], [%1], 16;\n" :: "r"(dst), "l"(src))
#define CP_COMMIT()    asm volatile("cp.async.commit_group;\n" ::)
#define CP_WAIT(N)     asm volatile("cp.async.wait_group %0;\n" :: "n"(N))
#define MMA_TF32(D, A, B)                                                       \
    asm volatile("mma.sync.aligned.m16n8k8.row.col.f32.tf32.tf32.f32 "          \
                 "{%0,%1,%2,%3}, {%4,%5,%6,%7}, {%8,%9}, {%0,%1,%2,%3};\n"      \
                 : "+f"((D)[0]), "+f"((D)[1]), "+f"((D)[2]), "+f"((D)[3])       \
                 : "r"((A)[0]), "r"((A)[1]), "r"((A)[2]), "r"((A)[3]),          \
                   "r"((B)[0]), "r"((B)[1]))

// smem strides (floats), padded for conflict-free fragment loads
#define ASTRIDE 20          // 16 + 4 pad   (A row stride; rows 16B aligned: 80B)
#define BSTRIDE 136         // 128 + 8 pad  (B row stride; rows 16B aligned: 544B)
#define AS_F (128 * ASTRIDE)        // 2560 floats per A stage
#define BS_F (16 * BSTRIDE)         // 2176 floats per B stage
#define STG1 (AS_F + 2 * BS_F)      // gemm1 stage (A + B1 + B3)
#define STG2 (AS_F + BS_F)          // gemm2 stage
#define SMEM1 (3 * STG1 * 4)        // 82944 B
#define SMEM2 (3 * STG2 * 4)        // 56832 B

// ---------------- init ------------------------------------------------------
__global__ void k_init() {
    int i = blockIdx.x * blockDim.x + threadIdx.x;
    if (i < NE) g_cnt[i] = 0;
    if (i < MAXSLOT) g_tok[i] = 0;
}

// ---------------- gate: logits + top-2 + softmax (fp32 exact) ---------------
__global__ void k_gate(const float* __restrict__ x, const float* __restrict__ Wg) {
    int gtid = blockIdx.x * blockDim.x + threadIdx.x;
    int t    = gtid >> 5;
    int lane = gtid & 31;
    if (t >= TT) return;

    const float* xr = x + (size_t)t * DD;
    float acc[NE];
#pragma unroll
    for (int e = 0; e < NE; e++) acc[e] = 0.0f;

    for (int k = lane; k < DD; k += 32) {
        float xv = xr[k];
        const float* wr = Wg + (size_t)k * NE;
        float4 w0 = *(const float4*)(wr);
        float4 w1 = *(const float4*)(wr + 4);
        acc[0] += xv * w0.x; acc[1] += xv * w0.y;
        acc[2] += xv * w0.z; acc[3] += xv * w0.w;
        acc[4] += xv * w1.x; acc[5] += xv * w1.y;
        acc[6] += xv * w1.z; acc[7] += xv * w1.w;
    }
#pragma unroll
    for (int off = 16; off > 0; off >>= 1)
#pragma unroll
        for (int e = 0; e < NE; e++)
            acc[e] += __shfl_xor_sync(0xffffffff, acc[e], off);

    if (lane == 0) {
        float l0 = acc[0]; int e0 = 0;
#pragma unroll
        for (int e = 1; e < NE; e++) if (acc[e] > l0) { l0 = acc[e]; e0 = e; }
        float l1 = -3.4e38f; int e1 = 0;
#pragma unroll
        for (int e = 0; e < NE; e++)
            if (e != e0 && acc[e] > l1) { l1 = acc[e]; e1 = e; }

        float wa = 1.0f / (1.0f + expf(l1 - l0));
        float wb = 1.0f - wa;

        int p0 = atomicAdd(&g_cnt[e0], 1);
        int p1 = atomicAdd(&g_cnt[e1], 1);
        int i0 = t * 2, i1 = t * 2 + 1;
        g_ce[i0] = e0; g_cpos[i0] = p0; g_cw[i0] = wa;
        g_ce[i1] = e1; g_cpos[i1] = p1; g_cw[i1] = wb;
    }
}

// ---------------- scan: per-expert bases padded to BM -----------------------
__global__ void k_scan() {
    int b = 0;
    g_padbase[0] = 0;
    for (int e = 0; e < NE; e++) {
        b += ((g_cnt[e] + BM - 1) / BM) * BM;
        g_padbase[e + 1] = b;
    }
}

// ---------------- scatter: slot tables --------------------------------------
__global__ void k_scatter() {
    int i = blockIdx.x * blockDim.x + threadIdx.x;
    if (i >= TT * 2) return;
    int e = g_ce[i];
    int slot = g_padbase[e] + g_cpos[i];
    g_tok[slot]  = i >> 1;
    g_slotof[i]  = slot;
}

// ---------------- gather: g_xg[slot] = x[tok[slot]] -------------------------
__global__ void k_gather(const float* __restrict__ x) {
    size_t i = (size_t)blockIdx.x * blockDim.x + threadIdx.x;
    int total = g_padbase[NE];
    if (i >= (size_t)total * (DD / 4)) return;
    int slot = (int)(i >> 9);          // DD/4 = 512
    int c    = (int)(i & 511);
    ((float4*)g_xg)[i] = ((const float4*)x)[((size_t)g_tok[slot] << 9) + c];
}

// ---------------- GEMM1: h = silu(Xg@w1[e]) * (Xg@w3[e])  [tf32 tensor] -----
// 128x128x16 block tile, 8 warps (2x4), warp tile 64x32, m16n8k8 tf32.
__global__ __launch_bounds__(256, 1) void k_gemm1(const float* __restrict__ w1,
                                                  const float* __restrict__ w3) {
    extern __shared__ float smem[];

    int total = g_padbase[NE];
    int m0 = blockIdx.y * BM;
    if (m0 >= total) return;
    int e = 0;
    while (g_padbase[e + 1] <= m0) e++;
    int n0 = blockIdx.x * 128;

    const float* w1e = w1 + (size_t)e * DD * HH;
    const float* w3e = w3 + (size_t)e * DD * HH;

    int tid = threadIdx.x;
    int lane = tid & 31, warp = tid >> 5;
    int wm = warp & 1, wn = warp >> 1;       // warp grid 2(M) x 4(N)
    int g = lane >> 2, tg = lane & 3;

    // loader indices
    int ai = tid >> 2, aq = tid & 3;          // A: 128 rows x 4 quads
    int bk = tid >> 5, bq = tid & 31;         // B: 16 rows x 32 quads
    const float* aSrc0 = g_xg + (size_t)(m0 + ai) * DD + aq * 4;
    const float* aSrc1 = g_xg + (size_t)(m0 + ai + 64) * DD + aq * 4;

    float acc1[4][4][4], acc3[4][4][4];
#pragma unroll
    for (int mt = 0; mt < 4; mt++)
#pragma unroll
        for (int nt = 0; nt < 4; nt++)
#pragma unroll
            for (int q = 0; q < 4; q++) { acc1[mt][nt][q] = 0.0f; acc3[mt][nt][q] = 0.0f; }

    auto prefetch = [&](int kt, int buf) {
        float* As  = smem + buf * STG1;
        float* B1s = As + AS_F;
        float* B3s = B1s + BS_F;
        int k0 = kt * 16;
        CP16(sh(As + ai * ASTRIDE + aq * 4),        aSrc0 + k0);
        CP16(sh(As + (ai + 64) * ASTRIDE + aq * 4), aSrc1 + k0);
        size_t o0 = (size_t)(k0 + bk)     * HH + n0 + bq * 4;
        size_t o1 = (size_t)(k0 + bk + 8) * HH + n0 + bq * 4;
        CP16(sh(B1s + bk * BSTRIDE + bq * 4),       w1e + o0);
        CP16(sh(B1s + (bk + 8) * BSTRIDE + bq * 4), w1e + o1);
        CP16(sh(B3s + bk * BSTRIDE + bq * 4),       w3e + o0);
        CP16(sh(B3s + (bk + 8) * BSTRIDE + bq * 4), w3e + o1);
    };

    auto compute = [&](int buf) {
        const float* As  = smem + buf * STG1;
        const float* B1s = As + AS_F;
        const float* B3s = B1s + BS_F;
#pragma unroll
        for (int ks = 0; ks < 2; ks++) {
            int kc = ks * 8 + tg;
            uint32_t a[4][4], b1[4][2], b3[4][2];
#pragma unroll
            for (int mt = 0; mt < 4; mt++) {
                int r = wm * 64 + mt * 16 + g;
                a[mt][0] = f2tf(As[r * ASTRIDE + kc]);
                a[mt][1] = f2tf(As[(r + 8) * ASTRIDE + kc]);
                a[mt][2] = f2tf(As[r * ASTRIDE + kc + 4]);
                a[mt][3] = f2tf(As[(r + 8) * ASTRIDE + kc + 4]);
            }
#pragma unroll
            for (int nt = 0; nt < 4; nt++) {
                int cn = wn * 32 + nt * 8 + g;
                b1[nt][0] = f2tf(B1s[kc * BSTRIDE + cn]);
                b1[nt][1] = f2tf(B1s[(kc + 4) * BSTRIDE + cn]);
                b3[nt][0] = f2tf(B3s[kc * BSTRIDE + cn]);
                b3[nt][1] = f2tf(B3s[(kc + 4) * BSTRIDE + cn]);
            }
#pragma unroll
            for (int mt = 0; mt < 4; mt++)
#pragma unroll
                for (int nt = 0; nt < 4; nt++) {
                    MMA_TF32(acc1[mt][nt], a[mt], b1[nt]);
                    MMA_TF32(acc3[mt][nt], a[mt], b3[nt]);
                }
        }
    };

    prefetch(0, 0); CP_COMMIT();
    prefetch(1, 1); CP_COMMIT();
    const int NSTEP = DD / 16;   // 128
    for (int kt = 0; kt < NSTEP; kt++) {
        if (kt + 2 < NSTEP)      { prefetch(kt + 2, (kt + 2) % 3); CP_COMMIT(); CP_WAIT(2); }
        else if (kt + 1 < NSTEP) { CP_WAIT(1); }
        else                     { CP_WAIT(0); }
        __syncthreads();
        compute(kt % 3);
        __syncthreads();
    }

    // epilogue: SwiGLU, store to g_h
#pragma unroll
    for (int mt = 0; mt < 4; mt++) {
        int r = m0 + wm * 64 + mt * 16 + g;
#pragma unroll
        for (int nt = 0; nt < 4; nt++) {
            int c = n0 + wn * 32 + nt * 8 + 2 * tg;
            float2 v0, v1;
            v0.x = fast_silu_mul(acc1[mt][nt][0], acc3[mt][nt][0]);
            v0.y = fast_silu_mul(acc1[mt][nt][1], acc3[mt][nt][1]);
            v1.x = fast_silu_mul(acc1[mt][nt][2], acc3[mt][nt][2]);
            v1.y = fast_silu_mul(acc1[mt][nt][3], acc3[mt][nt][3]);
            *(float2*)(g_h + (size_t)r * HH + c)       = v0;
            *(float2*)(g_h + (size_t)(r + 8) * HH + c) = v1;
        }
    }
}

// ---------------- GEMM2: y = h @ w2[e]  [tf32 tensor] -----------------------
__global__ __launch_bounds__(256, 1) void k_gemm2(const float* __restrict__ w2) {
    extern __shared__ float smem[];

    int total = g_padbase[NE];
    int m0 = blockIdx.y * BM;
    if (m0 >= total) return;
    int e = 0;
    while (g_padbase[e + 1] <= m0) e++;
    int n0 = blockIdx.x * 128;

    const float* w2e = w2 + (size_t)e * HH * DD;

    int tid = threadIdx.x;
    int lane = tid & 31, warp = tid >> 5;
    int wm = warp & 1, wn = warp >> 1;
    int g = lane >> 2, tg = lane & 3;

    int ai = tid >> 2, aq = tid & 3;
    int bk = tid >> 5, bq = tid & 31;
    const float* aSrc0 = g_h + (size_t)(m0 + ai) * HH + aq * 4;
    const float* aSrc1 = g_h + (size_t)(m0 + ai + 64) * HH + aq * 4;

    float acc[4][4][4];
#pragma unroll
    for (int mt = 0; mt < 4; mt++)
#pragma unroll
        for (int nt = 0; nt < 4; nt++)
#pragma unroll
            for (int q = 0; q < 4; q++) acc[mt][nt][q] = 0.0f;

    auto prefetch = [&](int kt, int buf) {
        float* As = smem + buf * STG2;
        float* Bs = As + AS_F;
        int k0 = kt * 16;
        CP16(sh(As + ai * ASTRIDE + aq * 4),        aSrc0 + k0);
        CP16(sh(As + (ai + 64) * ASTRIDE + aq * 4), aSrc1 + k0);
        CP16(sh(Bs + bk * BSTRIDE + bq * 4),       w2e + (size_t)(k0 + bk)     * DD + n0 + bq * 4);
        CP16(sh(Bs + (bk + 8) * BSTRIDE + bq * 4), w2e + (size_t)(k0 + bk + 8) * DD + n0 + bq * 4);
    };

    auto compute = [&](int buf) {
        const float* As = smem + buf * STG2;
        const float* Bs = As + AS_F;
#pragma unroll
        for (int ks = 0; ks < 2; ks++) {
            int kc = ks * 8 + tg;
            uint32_t a[4][4], b[4][2];
#pragma unroll
            for (int mt = 0; mt < 4; mt++) {
                int r = wm * 64 + mt * 16 + g;
                a[mt][0] = f2tf(As[r * ASTRIDE + kc]);
                a[mt][1] = f2tf(As[(r + 8) * ASTRIDE + kc]);
                a[mt][2] = f2tf(As[r * ASTRIDE + kc + 4]);
                a[mt][3] = f2tf(As[(r + 8) * ASTRIDE + kc + 4]);
            }
#pragma unroll
            for (int nt = 0; nt < 4; nt++) {
                int cn = wn * 32 + nt * 8 + g;
                b[nt][0] = f2tf(Bs[kc * BSTRIDE + cn]);
                b[nt][1] = f2tf(Bs[(kc + 4) * BSTRIDE + cn]);
            }
#pragma unroll
            for (int mt = 0; mt < 4; mt++)
#pragma unroll
                for (int nt = 0; nt < 4; nt++)
                    MMA_TF32(acc[mt][nt], a[mt], b[nt]);
        }
    };

    prefetch(0, 0); CP_COMMIT();
    prefetch(1, 1); CP_COMMIT();
    const int NSTEP = HH / 16;   // 352
    for (int kt = 0; kt < NSTEP; kt++) {
        if (kt + 2 < NSTEP)      { prefetch(kt + 2, (kt + 2) % 3); CP_COMMIT(); CP_WAIT(2); }
        else if (kt + 1 < NSTEP) { CP_WAIT(1); }
        else                     { CP_WAIT(0); }
        __syncthreads();
        compute(kt % 3);
        __syncthreads();
    }

#pragma unroll
    for (int mt = 0; mt < 4; mt++) {
        int r = m0 + wm * 64 + mt * 16 + g;
#pragma unroll
        for (int nt = 0; nt < 4; nt++) {
            int c = n0 + wn * 32 + nt * 8 + 2 * tg;
            *(float2*)(g_y + (size_t)r * DD + c)       = make_float2(acc[mt][nt][0], acc[mt][nt][1]);
            *(float2*)(g_y + (size_t)(r + 8) * DD + c) = make_float2(acc[mt][nt][2], acc[mt][nt][3]);
        }
    }
}

// ---------------- combine: out = next_r + w0*y[s0] + w1*y[s1] ---------------
__global__ void k_combine(float* __restrict__ out, const float* __restrict__ nr) {
    size_t i = (size_t)blockIdx.x * blockDim.x + threadIdx.x;
    if (i >= (size_t)TT * (DD / 4)) return;
    int t = (int)(i >> 9), c = (int)(i & 511);
    int s0 = g_slotof[2 * t], s1 = g_slotof[2 * t + 1];
    float w0 = g_cw[2 * t],  w1 = g_cw[2 * t + 1];
    const float4* y4 = (const float4*)g_y;
    float4 o = ((const float4*)nr)[i];
    float4 a = y4[((size_t)s0 << 9) + c];
    float4 b = y4[((size_t)s1 << 9) + c];
    o.x += w0 * a.x + w1 * b.x;
    o.y += w0 * a.y + w1 * b.y;
    o.z += w0 * a.z + w1 * b.z;
    o.w += w0 * a.w + w1 * b.w;
    ((float4*)out)[i] = o;
}

// ---------------- launch ----------------------------------------------------
extern "C" void kernel_launch(void* const* d_in, const int* in_sizes, int n_in,
                              void* d_out, int out_size) {
    const float* x  = (const float*)d_in[0];
    const float* Wg = (const float*)d_in[1];
    const float* w1 = (const float*)d_in[2];
    const float* w2 = (const float*)d_in[3];
    const float* w3 = (const float*)d_in[4];
    const float* nr = (const float*)d_in[5];
    float* out = (float*)d_out;

    cudaFuncSetAttribute(k_gemm1, cudaFuncAttributeMaxDynamicSharedMemorySize, SMEM1);
    cudaFuncSetAttribute(k_gemm2, cudaFuncAttributeMaxDynamicSharedMemorySize, SMEM2);

    k_init<<<(MAXSLOT + 255) / 256, 256>>>();
    k_gate<<<TT / 8, 256>>>(x, Wg);
    k_scan<<<1, 1>>>();
    k_scatter<<<(TT * 2) / 256, 256>>>();
    k_gather<<<(MAXSLOT * (DD / 4) + 255) / 256, 256>>>(x);

    dim3 g1(HH / 128, MAXSLOT / BM);     // (44, 72), n-fastest for L2 reuse
    k_gemm1<<<g1, 256, SMEM1>>>(w1, w3);

    dim3 g2(DD / 128, MAXSLOT / BM);     // (16, 72)
    k_gemm2<<<g2, 256, SMEM2>>>(w2);

    k_combine<<<(TT * (DD / 4) + 255) / 256, 256>>>(out, nr);
}